// round 9
// baseline (speedup 1.0000x reference)
#include <cuda_runtime.h>
#include <math.h>

// gdfn_region_batch: single kernel, one wave (608 = 4 CTA/SM * 152 SM).
// Light tiles: warp-autonomous scan+copy (no block barriers).
// Heavy tiles: collected in a smem worklist, then block-cooperative pipeline.

#define BATCH 8
#define CH 3
#define HH 512
#define WW 512
#define HP 514
#define TS 16
#define PR 22          // TS + 6
#define E2 20          // TS + 4
#define E1 18          // TS + 2
#define NTHREADS 256
#define NWARPS 8
#define TPB 32
#define NTILES (BATCH*TPB*TPB)   // 8192
#define GRIDSZ 608               // 4 CTA/SM * 152 SM, one wave

#define SP_SIZE   (CH*PR*PR)   // 1452
#define SR_SIZE   (E2*E2)      // 400
#define SMOD_SIZE (E2*E2)      // 400
#define SMEM_FLOATS (SP_SIZE + SR_SIZE + SMOD_SIZE)  // 2252 floats = 9008 B

__global__ __launch_bounds__(NTHREADS, 4)
void gdfn_fused_kernel(const float* __restrict__ img,
                       const float* __restrict__ noise,
                       const float* __restrict__ re_mask,
                       const int*   __restrict__ sel,
                       const int*   __restrict__ mix_sel,
                       float* __restrict__ out)
{
    const int tid  = threadIdx.x;
    const int warp = tid >> 5;
    const int lane = tid & 31;

    extern __shared__ float smem[];
    float* sp   = smem;                    // [CH][PR][PR] img_p = pad(img)+noise
    float* sr   = sp + SP_SIZE;            // [E2][E2]     img_r
    float* smod = sr + SR_SIZE;            // [E2][E2]     img_3d_mod

    __shared__ int s_count;
    __shared__ int s_list[32];             // <= ceil(8192/608)=14 tiles/block

    if (tid == 0) s_count = 0;
    __syncthreads();

    // ------------------------------------------------------------------
    // Pass 1 (warp-autonomous): scan + copy light tiles; queue heavy ones.
    // Block owns tiles {blockIdx.x + k*GRIDSZ}; warp takes k = warp, warp+8,...
    // ------------------------------------------------------------------
    for (int k = warp; ; k += NWARPS) {
        int tile = blockIdx.x + k * GRIDSZ;
        if (tile >= NTILES) break;
        const int b  = tile >> 10;
        const int h0 = ((tile >> 5) & 31) * TS;
        const int w0 = (tile & 31) * TS;

        const bool apply = (sel[b] != 0);
        bool light = true;
        if (apply) {
            int ok = 1;
            #pragma unroll
            for (int i = 0; i < 6; i++) {
                int idx = lane + 32 * i;           // 0..191
                int c   = idx >> 6;
                int rem = idx & 63;
                int r   = rem >> 2;
                int q   = rem & 3;
                size_t base = (((size_t)b * CH + c) * HH + (h0 + r)) * WW + w0 + q * 4;
                float4 rm = *(const float4*)(re_mask + base);
                if (rm.x != 1.0f || rm.y != 1.0f || rm.z != 1.0f || rm.w != 1.0f)
                    ok = 0;
            }
            light = __all_sync(0xffffffffu, ok);
        }

        if (light) {
            #pragma unroll
            for (int i = 0; i < 6; i++) {
                int idx = lane + 32 * i;
                int c   = idx >> 6;
                int rem = idx & 63;
                int r   = rem >> 2;
                int q   = rem & 3;
                size_t base = (((size_t)b * CH + c) * HH + (h0 + r)) * WW + w0 + q * 4;
                *(float4*)(out + base) = *(const float4*)(img + base);
            }
        } else if (lane == 0) {
            int slot = atomicAdd(&s_count, 1);
            s_list[slot] = tile;
        }
    }
    __syncthreads();

    // ------------------------------------------------------------------
    // Pass 2 (block-cooperative): heavy tiles from the worklist.
    // ------------------------------------------------------------------
    const int hn = s_count;
    for (int hi = 0; hi < hn; hi++) {
        __syncthreads();   // protect smem reuse across heavy iterations
        const int tile = s_list[hi];
        const int b  = tile >> 10;
        const int h0 = ((tile >> 5) & 31) * TS;
        const int w0 = (tile & 31) * TS;

        // Phase 1: img_p region (pad(img)+noise) into sp
        for (int i = tid; i < CH * PR * PR; i += NTHREADS) {
            int c   = i / (PR * PR);
            int rem = i % (PR * PR);
            int py  = rem / PR, px = rem % PR;
            int y = h0 - 2 + py;
            int x = w0 - 2 + px;
            float v = 0.0f;
            if (y >= 0 && y < HP && x >= 0 && x < HP) {
                v = noise[(((size_t)b * CH + c) * HP + y) * HP + x];
                int iy = y - 1, ix = x - 1;
                if (iy >= 0 && iy < HH && ix >= 0 && ix < WW)
                    v += img[(((size_t)b * CH + c) * HH + iy) * WW + ix];
            }
            sp[(c * PR + py) * PR + px] = v;
        }
        __syncthreads();

        const bool mix = (mix_sel[b] != 0);

        // Phase 2: img_r on E2 x E2 (img_3d recomputed later, not stored)
        for (int p = tid; p < E2 * E2; p += NTHREADS) {
            int r  = p / E2, cc = p % E2;
            int gy = h0 - 2 + r, gx = w0 - 2 + cc;
            float img_r = 0.0f;
            if (gy >= 0 && gy < HH && gx >= 0 && gx < WW) {
                float m[9], vsum[9];
                #pragma unroll
                for (int kk = 0; kk < 9; kk++) { m[kk] = 3.4e38f; vsum[kk] = 0.0f; }
                #pragma unroll
                for (int c = 0; c < CH; c++) {
                    float v[9]; float s = 0.0f;
                    #pragma unroll
                    for (int i = 0; i < 3; i++)
                        #pragma unroll
                        for (int j = 0; j < 3; j++) {
                            float tv = sp[(c * PR + r + i) * PR + cc + j];
                            v[i * 3 + j] = tv; s += tv; vsum[i * 3 + j] += tv;
                        }
                    float mean = s * (1.0f / 9.0f);
                    float sd2 = 0.0f;
                    #pragma unroll
                    for (int kk = 0; kk < 9; kk++) {
                        float d = v[kk] - mean; v[kk] = d; sd2 += d * d;
                    }
                    float inv = __fdividef(4.0f, sd2);   // 1/(2*var_ddof1)
                    #pragma unroll
                    for (int kk = 0; kk < 9; kk++) {
                        float wv = __expf(-v[kk] * v[kk] * inv);
                        m[kk] = fminf(m[kk], wv);
                    }
                }
                float num = 0.0f, den = 0.0f;
                #pragma unroll
                for (int kk = 0; kk < 9; kk++) { num += m[kk] * vsum[kk]; den += m[kk]; }
                img_r = __fdividef(num, den);
            }
            sr[r * E2 + cc] = img_r;
        }
        __syncthreads();

        // Phase 3: argmin/argmax (first-index tie-break); recompute m[id]
        for (int p = tid; p < E1 * E1; p += NTHREADS) {
            int r  = 1 + p / E1, cc = 1 + p % E1;
            int gy = h0 - 2 + r, gx = w0 - 2 + cc;
            float mv = 0.0f;
            if (gy >= 0 && gy < HH && gx >= 0 && gx < WW) {
                float bmin = 3.4e38f, bmax = -3.4e38f;
                int kmin = 0, kmax = 0;
                #pragma unroll
                for (int i = 0; i < 3; i++)
                    #pragma unroll
                    for (int j = 0; j < 3; j++) {
                        float val = sr[(r - 1 + i) * E2 + (cc - 1 + j)];
                        int kk = i * 3 + j;
                        if (val < bmin) { bmin = val; kmin = kk; }
                        if (val > bmax) { bmax = val; kmax = kk; }
                    }
                int id = mix ? kmax : kmin;
                int di = id / 3, dj = id % 3;
                mv = 3.4e38f;
                #pragma unroll
                for (int c = 0; c < CH; c++) {
                    float v[9]; float s = 0.0f;
                    #pragma unroll
                    for (int i = 0; i < 3; i++)
                        #pragma unroll
                        for (int j = 0; j < 3; j++) {
                            float tv = sp[(c * PR + r + i) * PR + cc + j];
                            v[i * 3 + j] = tv; s += tv;
                        }
                    float mean = s * (1.0f / 9.0f);
                    float sd2 = 0.0f;
                    #pragma unroll
                    for (int kk = 0; kk < 9; kk++) {
                        float d = v[kk] - mean; v[kk] = d; sd2 += d * d;
                    }
                    float inv = __fdividef(4.0f, sd2);
                    float dsel = v[di * 3 + dj];
                    float wv = __expf(-dsel * dsel * inv);
                    mv = fminf(mv, wv);
                }
            }
            smod[r * E2 + cc] = mv;
        }
        __syncthreads();

        // Phase 4: img_mod and final compose (256 px = 1 per thread)
        {
            int ty = tid >> 4, tx = tid & 15;
            int gy = h0 + ty, gx = w0 + tx;
            float mm[9]; float den = 0.0f;
            #pragma unroll
            for (int i = 0; i < 3; i++)
                #pragma unroll
                for (int j = 0; j < 3; j++) {
                    float tv = smod[(ty + 1 + i) * E2 + (tx + 1 + j)];
                    mm[i * 3 + j] = tv; den += tv;
                }
            float rden = __fdividef(1.0f, den);
            #pragma unroll
            for (int c = 0; c < CH; c++) {
                float num = 0.0f;
                #pragma unroll
                for (int i = 0; i < 3; i++)
                    #pragma unroll
                    for (int j = 0; j < 3; j++)
                        num += sp[(c * PR + ty + 2 + i) * PR + tx + 2 + j] * mm[i * 3 + j];
                float imod = num * rden;
                size_t gidx = (((size_t)b * CH + c) * HH + gy) * WW + gx;
                float im = img[gidx];
                float re = re_mask[gidx];
                out[gidx] = imod * (1.0f - re) + im * re;  // exact where re==1
            }
        }
    }
}

extern "C" void kernel_launch(void* const* d_in, const int* in_sizes, int n_in,
                              void* d_out, int out_size)
{
    const float* img     = (const float*)d_in[0];
    const float* noise   = (const float*)d_in[1];
    const float* re_mask = (const float*)d_in[2];
    const int*   sel     = (const int*)d_in[3];
    const int*   mix_sel = (const int*)d_in[4];
    float* out = (float*)d_out;

    size_t smem = SMEM_FLOATS * sizeof(float);
    cudaFuncSetAttribute(gdfn_fused_kernel,
                         cudaFuncAttributeMaxDynamicSharedMemorySize, (int)smem);

    gdfn_fused_kernel<<<GRIDSZ, NTHREADS, smem>>>(img, noise, re_mask, sel,
                                                  mix_sel, out);
}

// round 11
// speedup vs baseline: 1.4232x; 1.4232x over previous
#include <cuda_runtime.h>
#include <math.h>

// gdfn_region_batch:
//  A) copy_scan: warp-per-16x16-tile; copies light tiles, compacts heavy ones.
//  B) heavy: 608 persistent blocks over the compacted list; exp-reduced math
//     (min_c exp(x) == exp(min_c x), bit-exact); self-resets counters.

#define BATCH 8
#define CH 3
#define HH 512
#define WW 512
#define HP 514
#define TS 16
#define PR 22          // TS + 6
#define E2 20          // TS + 4
#define E1 18          // TS + 2
#define NTHREADS 256
#define TPB 32
#define NTILES (BATCH*TPB*TPB)   // 8192
#define GRIDA (NTILES/8)         // 1024 blocks, 8 warps = 8 tiles each
#define GRIDB 608                // 4 CTA/SM * 152 SM

#define SP_SIZE   (CH*PR*PR)   // 1452
#define SR_SIZE   (E2*E2)      // 400
#define SMOD_SIZE (E2*E2)      // 400
#define SMEM_FLOATS (SP_SIZE + SR_SIZE + SMOD_SIZE)  // 2252 floats = 9008 B

__device__ int g_count;          // zero-init; heavy kernel self-resets
__device__ int g_done;
__device__ int g_list[NTILES];

// ---------------------------------------------------------------------------
// Kernel A: warp-autonomous scan + copy; push heavy tiles.
// ---------------------------------------------------------------------------
__global__ __launch_bounds__(NTHREADS)
void copy_scan_kernel(const float* __restrict__ img,
                      const float* __restrict__ re_mask,
                      const int*   __restrict__ sel,
                      float* __restrict__ out)
{
    const int warp = threadIdx.x >> 5;
    const int lane = threadIdx.x & 31;
    const int tile = blockIdx.x * 8 + warp;

    const int b  = tile >> 10;
    const int h0 = ((tile >> 5) & 31) * TS;
    const int w0 = (tile & 31) * TS;

    const bool apply = (sel[b] != 0);

    // lane handles 6 float4s: idx = lane + 32*i -> (c, r, q)
    size_t base[6];
    #pragma unroll
    for (int i = 0; i < 6; i++) {
        int idx = lane + 32 * i;
        int c   = idx >> 6;
        int rem = idx & 63;
        int r   = rem >> 2;
        int q   = rem & 3;
        base[i] = (((size_t)b * CH + c) * HH + (h0 + r)) * WW + w0 + q * 4;
    }

    bool light = true;
    if (apply) {
        int ok = 1;
        #pragma unroll
        for (int i = 0; i < 6; i++) {
            float4 rm = *(const float4*)(re_mask + base[i]);
            if (rm.x != 1.0f || rm.y != 1.0f || rm.z != 1.0f || rm.w != 1.0f)
                ok = 0;
        }
        light = __all_sync(0xffffffffu, ok);
    }

    if (light) {
        #pragma unroll
        for (int i = 0; i < 6; i++)
            *(float4*)(out + base[i]) = *(const float4*)(img + base[i]);
    } else if (lane == 0) {
        int slot = atomicAdd(&g_count, 1);
        g_list[slot] = tile;
    }
}

// ---------------------------------------------------------------------------
// Kernel B: persistent heavy-tile processor over the compacted list.
// ---------------------------------------------------------------------------
__global__ __launch_bounds__(NTHREADS)
void heavy_kernel(const float* __restrict__ img,
                  const float* __restrict__ noise,
                  const float* __restrict__ re_mask,
                  const int*   __restrict__ mix_sel,
                  float* __restrict__ out)
{
    const int tid = threadIdx.x;
    const int cnt = g_count;

    extern __shared__ float smem[];
    float* sp   = smem;                    // [CH][PR][PR] img_p = pad(img)+noise
    float* sr   = sp + SP_SIZE;            // [E2][E2]     img_r
    float* smod = sr + SR_SIZE;            // [E2][E2]     img_3d_mod

    for (int hi = blockIdx.x; hi < cnt; hi += GRIDB) {
        __syncthreads();   // smem reuse guard across iterations
        const int tile = g_list[hi];
        const int b  = tile >> 10;
        const int h0 = ((tile >> 5) & 31) * TS;
        const int w0 = (tile & 31) * TS;

        // Phase 1: img_p region (pad(img)+noise)
        for (int i = tid; i < CH * PR * PR; i += NTHREADS) {
            int c   = i / (PR * PR);
            int rem = i % (PR * PR);
            int py  = rem / PR, px = rem % PR;
            int y = h0 - 2 + py;
            int x = w0 - 2 + px;
            float v = 0.0f;
            if (y >= 0 && y < HP && x >= 0 && x < HP) {
                v = noise[(((size_t)b * CH + c) * HP + y) * HP + x];
                int iy = y - 1, ix = x - 1;
                if (iy >= 0 && iy < HH && ix >= 0 && ix < WW)
                    v += img[(((size_t)b * CH + c) * HH + iy) * WW + ix];
            }
            sp[(c * PR + py) * PR + px] = v;
        }
        __syncthreads();

        const bool mix = (mix_sel[b] != 0);

        // Phase 2: img_r on E2 x E2.  m[k] = exp(-max_c(d^2*inv_c))  (bit-exact
        // transform of min_c exp(-d^2*inv_c): exp is monotone).
        for (int p = tid; p < E2 * E2; p += NTHREADS) {
            int r  = p / E2, cc = p % E2;
            int gy = h0 - 2 + r, gx = w0 - 2 + cc;
            float img_r = 0.0f;
            if (gy >= 0 && gy < HH && gx >= 0 && gx < WW) {
                float t[9], vsum[9];
                #pragma unroll
                for (int k = 0; k < 9; k++) { t[k] = -3.4e38f; vsum[k] = 0.0f; }
                #pragma unroll
                for (int c = 0; c < CH; c++) {
                    float v[9]; float s = 0.0f;
                    #pragma unroll
                    for (int i = 0; i < 3; i++)
                        #pragma unroll
                        for (int j = 0; j < 3; j++) {
                            float tv = sp[(c * PR + r + i) * PR + cc + j];
                            v[i * 3 + j] = tv; s += tv; vsum[i * 3 + j] += tv;
                        }
                    float mean = s * (1.0f / 9.0f);
                    float sd2 = 0.0f;
                    #pragma unroll
                    for (int k = 0; k < 9; k++) {
                        float d = v[k] - mean; v[k] = d; sd2 += d * d;
                    }
                    float inv = __fdividef(4.0f, sd2);   // 1/(2*var_ddof1)
                    #pragma unroll
                    for (int k = 0; k < 9; k++)
                        t[k] = fmaxf(t[k], v[k] * v[k] * inv);
                }
                float num = 0.0f, den = 0.0f;
                #pragma unroll
                for (int k = 0; k < 9; k++) {
                    float m = __expf(-t[k]);
                    num += m * vsum[k]; den += m;
                }
                img_r = __fdividef(num, den);
            }
            sr[r * E2 + cc] = img_r;
        }
        __syncthreads();

        // Phase 3: argmin/argmax of img_r 3x3 (first-index tie-break);
        // recompute selected weight: exp(-max_c(d_sel^2*inv_c)), 1 exp.
        for (int p = tid; p < E1 * E1; p += NTHREADS) {
            int r  = 1 + p / E1, cc = 1 + p % E1;
            int gy = h0 - 2 + r, gx = w0 - 2 + cc;
            float mv = 0.0f;
            if (gy >= 0 && gy < HH && gx >= 0 && gx < WW) {
                float bmin = 3.4e38f, bmax = -3.4e38f;
                int kmin = 0, kmax = 0;
                #pragma unroll
                for (int i = 0; i < 3; i++)
                    #pragma unroll
                    for (int j = 0; j < 3; j++) {
                        float val = sr[(r - 1 + i) * E2 + (cc - 1 + j)];
                        int k = i * 3 + j;
                        if (val < bmin) { bmin = val; kmin = k; }
                        if (val > bmax) { bmax = val; kmax = k; }
                    }
                int id = mix ? kmax : kmin;
                int di = id / 3, dj = id % 3;
                float tmax = -3.4e38f;
                #pragma unroll
                for (int c = 0; c < CH; c++) {
                    float v[9]; float s = 0.0f;
                    #pragma unroll
                    for (int i = 0; i < 3; i++)
                        #pragma unroll
                        for (int j = 0; j < 3; j++) {
                            float tv = sp[(c * PR + r + i) * PR + cc + j];
                            v[i * 3 + j] = tv; s += tv;
                        }
                    float mean = s * (1.0f / 9.0f);
                    float sd2 = 0.0f;
                    #pragma unroll
                    for (int k = 0; k < 9; k++) {
                        float d = v[k] - mean; v[k] = d; sd2 += d * d;
                    }
                    float inv = __fdividef(4.0f, sd2);
                    float dsel = v[di * 3 + dj];
                    tmax = fmaxf(tmax, dsel * dsel * inv);
                }
                mv = __expf(-tmax);
            }
            smod[r * E2 + cc] = mv;
        }
        __syncthreads();

        // Phase 4: img_mod and final compose (256 px = 1 per thread)
        {
            int ty = tid >> 4, tx = tid & 15;
            int gy = h0 + ty, gx = w0 + tx;
            float mm[9]; float den = 0.0f;
            #pragma unroll
            for (int i = 0; i < 3; i++)
                #pragma unroll
                for (int j = 0; j < 3; j++) {
                    float tv = smod[(ty + 1 + i) * E2 + (tx + 1 + j)];
                    mm[i * 3 + j] = tv; den += tv;
                }
            float rden = __fdividef(1.0f, den);
            #pragma unroll
            for (int c = 0; c < CH; c++) {
                float num = 0.0f;
                #pragma unroll
                for (int i = 0; i < 3; i++)
                    #pragma unroll
                    for (int j = 0; j < 3; j++)
                        num += sp[(c * PR + ty + 2 + i) * PR + tx + 2 + j] * mm[i * 3 + j];
                float imod = num * rden;
                size_t gidx = (((size_t)b * CH + c) * HH + gy) * WW + gx;
                float im = img[gidx];
                float re = re_mask[gidx];
                out[gidx] = imod * (1.0f - re) + im * re;  // exact where re==1
            }
        }
    }

    // Self-reset for next replay: last-finishing block zeroes the counters.
    __syncthreads();
    if (tid == 0) {
        __threadfence();
        int old = atomicAdd(&g_done, 1);
        if (old == GRIDB - 1) { g_count = 0; g_done = 0; }
    }
}

extern "C" void kernel_launch(void* const* d_in, const int* in_sizes, int n_in,
                              void* d_out, int out_size)
{
    const float* img     = (const float*)d_in[0];
    const float* noise   = (const float*)d_in[1];
    const float* re_mask = (const float*)d_in[2];
    const int*   sel     = (const int*)d_in[3];
    const int*   mix_sel = (const int*)d_in[4];
    float* out = (float*)d_out;

    size_t smem = SMEM_FLOATS * sizeof(float);
    cudaFuncSetAttribute(heavy_kernel,
                         cudaFuncAttributeMaxDynamicSharedMemorySize, (int)smem);

    copy_scan_kernel<<<GRIDA, NTHREADS>>>(img, re_mask, sel, out);
    heavy_kernel<<<GRIDB, NTHREADS, smem>>>(img, noise, re_mask, mix_sel, out);
}